// round 1
// baseline (speedup 1.0000x reference)
#include <cuda_runtime.h>
#include <math.h>

// Problem constants
#define N_SEQ  1024
#define B_SZ   4
#define C_DIM  1024
#define H_NUM  16
#define HD     64
#define BH     64          // B*H
#define M_ROWS 4096        // N*B
#define LOGMAX 4.6051701859880913680f  // log(100)

// Scratch (static device arrays -- no allocations allowed)
__device__ float g_qs[BH * N_SEQ * HD];  // [bh][n][d]
__device__ float g_ks[BH * N_SEQ * HD];
__device__ float g_vs[BH * N_SEQ * HD];
__device__ float g_x [M_ROWS * C_DIM];   // (N,B,C) flattened, row m = n*B+b

// ---------------------------------------------------------------------------
// Kernel 1: fused QKV projection. C[m][j] = sum_c A[m][c]*W[j][c] + bias[j]
// scattered into per-head layout [bh][n][d]. blockIdx.z selects q/k/v.
// 128x128x16 tile, 256 threads, 8x8 microtile (split 4+4).
// ---------------------------------------------------------------------------
__global__ void __launch_bounds__(256) proj_kernel(
    const float* __restrict__ q_in, const float* __restrict__ k_in,
    const float* __restrict__ v_in, const float* __restrict__ W,
    const float* __restrict__ bias)
{
    __shared__ float As[128][17];
    __shared__ float Bs[128][17];

    const int z = blockIdx.z;
    const float* A  = (z == 0) ? q_in : (z == 1) ? k_in : v_in;
    const float* Wp = W + z * C_DIM * C_DIM;
    const float* bp = bias + z * C_DIM;
    float* outp = (z == 0) ? g_qs : (z == 1) ? g_ks : g_vs;

    const int m0 = blockIdx.y * 128;
    const int n0 = blockIdx.x * 128;
    const int tid = threadIdx.x;
    const int ty4 = (tid >> 4) * 4;
    const int tx4 = (tid & 15) * 4;

    float acc[8][8];
#pragma unroll
    for (int i = 0; i < 8; i++)
#pragma unroll
        for (int j = 0; j < 8; j++) acc[i][j] = 0.f;

    for (int k0 = 0; k0 < C_DIM; k0 += 16) {
        __syncthreads();
#pragma unroll
        for (int u = 0; u < 2; u++) {
            int f = tid + 256 * u;
            int r = f >> 2;
            int c4 = (f & 3) << 2;
            float4 va = *(const float4*)(A  + (m0 + r) * C_DIM + k0 + c4);
            As[r][c4 + 0] = va.x; As[r][c4 + 1] = va.y;
            As[r][c4 + 2] = va.z; As[r][c4 + 3] = va.w;
            float4 vb = *(const float4*)(Wp + (n0 + r) * C_DIM + k0 + c4);
            Bs[r][c4 + 0] = vb.x; Bs[r][c4 + 1] = vb.y;
            Bs[r][c4 + 2] = vb.z; Bs[r][c4 + 3] = vb.w;
        }
        __syncthreads();
#pragma unroll
        for (int kk = 0; kk < 16; kk++) {
            float a[8], b[8];
#pragma unroll
            for (int i = 0; i < 4; i++) {
                a[i]     = As[ty4 + i][kk];
                a[i + 4] = As[64 + ty4 + i][kk];
                b[i]     = Bs[tx4 + i][kk];
                b[i + 4] = Bs[64 + tx4 + i][kk];
            }
#pragma unroll
            for (int i = 0; i < 8; i++)
#pragma unroll
                for (int j = 0; j < 8; j++)
                    acc[i][j] = fmaf(a[i], b[j], acc[i][j]);
        }
    }

#pragma unroll
    for (int i = 0; i < 8; i++) {
        int lrow = (i < 4) ? (ty4 + i) : (64 + ty4 + i - 4);
        int m = m0 + lrow;
        int n  = m >> 2;     // row m = n*B + b, B=4
        int bb = m & 3;
#pragma unroll
        for (int j = 0; j < 8; j++) {
            int lcol = (j < 4) ? (tx4 + j) : (64 + tx4 + j - 4);
            int col = n0 + lcol;
            int h = col >> 6;
            int d = col & 63;
            outp[(((bb * H_NUM + h) * N_SEQ) + n) * HD + d] = acc[i][j] + bp[col];
        }
    }
}

// ---------------------------------------------------------------------------
// Kernel 2: L2-normalize each 64-vector of g_qs and g_ks.
// Fold exp(min(logit_scale, log100)) into q. One warp per row.
// ---------------------------------------------------------------------------
__global__ void __launch_bounds__(256) norm_kernel(const float* __restrict__ logit_scale)
{
    int wid = (blockIdx.x * blockDim.x + threadIdx.x) >> 5;
    int lane = threadIdx.x & 31;
    const int rows_per_tensor = BH * N_SEQ;  // 65536
    if (wid >= 2 * rows_per_tensor) return;
    int which = wid >= rows_per_tensor;
    int row = wid - which * rows_per_tensor;   // = bh*N + n
    float* ptr = (which ? g_ks : g_qs) + (size_t)row * HD;

    float x0 = ptr[lane];
    float x1 = ptr[lane + 32];
    float ss = x0 * x0 + x1 * x1;
#pragma unroll
    for (int o = 16; o > 0; o >>= 1) ss += __shfl_xor_sync(0xffffffffu, ss, o);
    float scale = 1.0f / fmaxf(sqrtf(ss), 1e-12f);
    if (!which) {
        int h = (row >> 10) & 15;   // bh = row>>10; h = bh % 16
        scale *= expf(fminf(logit_scale[h], LOGMAX));
    }
    ptr[lane]      = x0 * scale;
    ptr[lane + 32] = x1 * scale;
}

// ---------------------------------------------------------------------------
// Kernel 3: flash attention. Block = (128 queries) x (one head).
// Key tiles of 64, online softmax, P staged through smem.
// ---------------------------------------------------------------------------
#define QS(r, d) Qs[(r) * 65 + (d)]
#define KS(r, d) Ks[(r) * 65 + (d)]
#define VS(r, d) Vs[(r) * 65 + (d)]
#define PS(r, d) Ps[(r) * 65 + (d)]
#define ATTN_SMEM_BYTES (65 * (128 + 64 + 64 + 128) * 4)  // 99840 bytes

__global__ void __launch_bounds__(256, 2) attn_kernel()
{
    extern __shared__ float sm[];
    float* Qs = sm;                   // [128][65]
    float* Ks = Qs + 128 * 65;        // [64][65]
    float* Vs = Ks + 64 * 65;         // [64][65]
    float* Ps = Vs + 64 * 65;         // [128][65]

    const int bh = blockIdx.y;
    const int n0 = blockIdx.x * 128;
    const int tid = threadIdx.x;
    const int ty4 = (tid >> 4) * 4;
    const int tx4 = (tid & 15) * 4;

    const float* qbase = g_qs + ((size_t)bh * N_SEQ + n0) * HD;
    const float* kbase = g_ks + (size_t)bh * N_SEQ * HD;
    const float* vbase = g_vs + (size_t)bh * N_SEQ * HD;

    int rows[8];
#pragma unroll
    for (int i = 0; i < 4; i++) { rows[i] = ty4 + i; rows[i + 4] = 64 + ty4 + i; }

    // Load Q tile 128x64 (coalesced float4)
#pragma unroll
    for (int u = 0; u < 8; u++) {
        int f = tid + 256 * u;
        int r = f >> 4;
        int d0 = (f & 15) << 2;
        float4 v = *(const float4*)(qbase + r * HD + d0);
        QS(r, d0 + 0) = v.x; QS(r, d0 + 1) = v.y;
        QS(r, d0 + 2) = v.z; QS(r, d0 + 3) = v.w;
    }

    float m_[8], l_[8], o_[8][4];
#pragma unroll
    for (int i = 0; i < 8; i++) {
        m_[i] = -3.0e38f; l_[i] = 0.f;
#pragma unroll
        for (int j = 0; j < 4; j++) o_[i][j] = 0.f;
    }

    for (int kt = 0; kt < N_SEQ / 64; kt++) {
        __syncthreads();  // prior PV done (and Q ready on first iter)
        const float* kb = kbase + kt * 64 * HD;
        const float* vb = vbase + kt * 64 * HD;
#pragma unroll
        for (int u = 0; u < 4; u++) {
            int f = tid + 256 * u;
            int r = f >> 4;
            int d0 = (f & 15) << 2;
            float4 vk = *(const float4*)(kb + r * HD + d0);
            KS(r, d0 + 0) = vk.x; KS(r, d0 + 1) = vk.y;
            KS(r, d0 + 2) = vk.z; KS(r, d0 + 3) = vk.w;
            float4 vv = *(const float4*)(vb + r * HD + d0);
            VS(r, d0 + 0) = vv.x; VS(r, d0 + 1) = vv.y;
            VS(r, d0 + 2) = vv.z; VS(r, d0 + 3) = vv.w;
        }
        __syncthreads();

        // S = Q . K^T  (scale already folded into q)
        float s[8][4];
#pragma unroll
        for (int i = 0; i < 8; i++)
#pragma unroll
            for (int j = 0; j < 4; j++) s[i][j] = 0.f;
#pragma unroll 8
        for (int d = 0; d < HD; d++) {
            float a[8], b[4];
#pragma unroll
            for (int i = 0; i < 8; i++) a[i] = QS(rows[i], d);
#pragma unroll
            for (int j = 0; j < 4; j++) b[j] = KS(tx4 + j, d);
#pragma unroll
            for (int i = 0; i < 8; i++)
#pragma unroll
                for (int j = 0; j < 4; j++) s[i][j] = fmaf(a[i], b[j], s[i][j]);
        }

        // Online softmax (row reductions across the 16 tx lanes)
#pragma unroll
        for (int i = 0; i < 8; i++) {
            float tmax = fmaxf(fmaxf(s[i][0], s[i][1]), fmaxf(s[i][2], s[i][3]));
#pragma unroll
            for (int o = 8; o > 0; o >>= 1)
                tmax = fmaxf(tmax, __shfl_xor_sync(0xffffffffu, tmax, o));
            float mn = fmaxf(m_[i], tmax);
            float corr = __expf(m_[i] - mn);
            float rs = 0.f;
#pragma unroll
            for (int j = 0; j < 4; j++) { s[i][j] = __expf(s[i][j] - mn); rs += s[i][j]; }
#pragma unroll
            for (int o = 8; o > 0; o >>= 1)
                rs += __shfl_xor_sync(0xffffffffu, rs, o);
            l_[i] = l_[i] * corr + rs;
            m_[i] = mn;
#pragma unroll
            for (int j = 0; j < 4; j++) o_[i][j] *= corr;
        }

        // Stage P
#pragma unroll
        for (int i = 0; i < 8; i++)
#pragma unroll
            for (int j = 0; j < 4; j++) PS(rows[i], tx4 + j) = s[i][j];
        __syncthreads();

        // O += P . V
#pragma unroll 8
        for (int k = 0; k < 64; k++) {
            float a[8], b[4];
#pragma unroll
            for (int i = 0; i < 8; i++) a[i] = PS(rows[i], k);
#pragma unroll
            for (int j = 0; j < 4; j++) b[j] = VS(k, tx4 + j);
#pragma unroll
            for (int i = 0; i < 8; i++)
#pragma unroll
                for (int j = 0; j < 4; j++) o_[i][j] = fmaf(a[i], b[j], o_[i][j]);
        }
    }

    // Epilogue: divide by l, write to (N,B,C) layout for output GEMM
    const int bb = bh >> 4;
    const int h  = bh & 15;
#pragma unroll
    for (int i = 0; i < 8; i++) {
        float inv = 1.0f / l_[i];
        int n = n0 + rows[i];
#pragma unroll
        for (int j = 0; j < 4; j++) {
            g_x[((size_t)n * B_SZ + bb) * C_DIM + h * HD + tx4 + j] = o_[i][j] * inv;
        }
    }
}

// ---------------------------------------------------------------------------
// Kernel 4: output projection out = x @ out_w^T + out_b  (linear store)
// ---------------------------------------------------------------------------
__global__ void __launch_bounds__(256) out_kernel(
    const float* __restrict__ W, const float* __restrict__ bias,
    float* __restrict__ dout)
{
    __shared__ float As[128][17];
    __shared__ float Bs[128][17];

    const int m0 = blockIdx.y * 128;
    const int n0 = blockIdx.x * 128;
    const int tid = threadIdx.x;
    const int ty4 = (tid >> 4) * 4;
    const int tx4 = (tid & 15) * 4;

    float acc[8][8];
#pragma unroll
    for (int i = 0; i < 8; i++)
#pragma unroll
        for (int j = 0; j < 8; j++) acc[i][j] = 0.f;

    for (int k0 = 0; k0 < C_DIM; k0 += 16) {
        __syncthreads();
#pragma unroll
        for (int u = 0; u < 2; u++) {
            int f = tid + 256 * u;
            int r = f >> 2;
            int c4 = (f & 3) << 2;
            float4 va = *(const float4*)(g_x + (m0 + r) * C_DIM + k0 + c4);
            As[r][c4 + 0] = va.x; As[r][c4 + 1] = va.y;
            As[r][c4 + 2] = va.z; As[r][c4 + 3] = va.w;
            float4 vb = *(const float4*)(W + (n0 + r) * C_DIM + k0 + c4);
            Bs[r][c4 + 0] = vb.x; Bs[r][c4 + 1] = vb.y;
            Bs[r][c4 + 2] = vb.z; Bs[r][c4 + 3] = vb.w;
        }
        __syncthreads();
#pragma unroll
        for (int kk = 0; kk < 16; kk++) {
            float a[8], b[8];
#pragma unroll
            for (int i = 0; i < 4; i++) {
                a[i]     = As[ty4 + i][kk];
                a[i + 4] = As[64 + ty4 + i][kk];
                b[i]     = Bs[tx4 + i][kk];
                b[i + 4] = Bs[64 + tx4 + i][kk];
            }
#pragma unroll
            for (int i = 0; i < 8; i++)
#pragma unroll
                for (int j = 0; j < 8; j++)
                    acc[i][j] = fmaf(a[i], b[j], acc[i][j]);
        }
    }

#pragma unroll
    for (int i = 0; i < 8; i++) {
        int m = m0 + ((i < 4) ? (ty4 + i) : (64 + ty4 + i - 4));
#pragma unroll
        for (int j = 0; j < 8; j++) {
            int col = n0 + ((j < 4) ? (tx4 + j) : (64 + tx4 + j - 4));
            dout[(size_t)m * C_DIM + col] = acc[i][j] + bias[col];
        }
    }
}

// ---------------------------------------------------------------------------
extern "C" void kernel_launch(void* const* d_in, const int* in_sizes, int n_in,
                              void* d_out, int out_size)
{
    const float* q     = (const float*)d_in[0];
    const float* k     = (const float*)d_in[1];
    const float* v     = (const float*)d_in[2];
    const float* w_in  = (const float*)d_in[3];
    const float* b_in  = (const float*)d_in[4];
    const float* ls    = (const float*)d_in[5];
    const float* w_out = (const float*)d_in[6];
    const float* b_out = (const float*)d_in[7];
    float* out = (float*)d_out;

    // Attention kernel needs ~97.5 KB dynamic smem (> 48KB default).
    // Not a stream op; executes immediately even under graph capture.
    cudaFuncSetAttribute(attn_kernel,
                         cudaFuncAttributeMaxDynamicSharedMemorySize,
                         ATTN_SMEM_BYTES);

    proj_kernel<<<dim3(C_DIM / 128, M_ROWS / 128, 3), 256>>>(q, k, v, w_in, b_in);
    norm_kernel<<<(2 * BH * N_SEQ) / 8, 256>>>(ls);
    attn_kernel<<<dim3(N_SEQ / 128, BH), 256, ATTN_SMEM_BYTES>>>();
    out_kernel<<<dim3(C_DIM / 128, M_ROWS / 128), 256>>>(w_out, b_out, out);
}

// round 5
// speedup vs baseline: 1.3909x; 1.3909x over previous
#include <cuda_runtime.h>
#include <math.h>
#include <stdint.h>

// Problem constants
#define N_SEQ  1024
#define B_SZ   4
#define C_DIM  1024
#define H_NUM  16
#define HD     64
#define BH     64          // B*H
#define M_ROWS 4096        // N*B
#define LOGMAX 4.6051701859880913680f  // log(100)

// Scratch (static device arrays -- no allocations allowed)
__device__ float g_qs[BH * N_SEQ * HD];  // [bh][n][d]
__device__ float g_ks[BH * N_SEQ * HD];
__device__ float g_vs[BH * N_SEQ * HD];
__device__ float g_x [M_ROWS * C_DIM];   // (N,B,C) flattened, row m = n*B+b

// ---------------------------------------------------------------------------
// Helpers (plain-target PTX only)
// ---------------------------------------------------------------------------
__device__ __forceinline__ float tf32_rna(float x) {
    uint32_t r;
    asm("cvt.rna.tf32.f32 %0, %1;" : "=r"(r) : "f"(x));
    return __uint_as_float(r);
}

__device__ __forceinline__ void mma_tf32(float* d, const uint32_t* a,
                                         uint32_t b0, uint32_t b1) {
    asm volatile(
        "mma.sync.aligned.m16n8k8.row.col.f32.tf32.tf32.f32 "
        "{%0,%1,%2,%3}, {%4,%5,%6,%7}, {%8,%9}, {%0,%1,%2,%3};"
        : "+f"(d[0]), "+f"(d[1]), "+f"(d[2]), "+f"(d[3])
        : "r"(a[0]), "r"(a[1]), "r"(a[2]), "r"(a[3]), "r"(b0), "r"(b1));
}

// ---------------------------------------------------------------------------
// Tensor-core GEMM with 3xTF32 (near-fp32 accuracy):
//   C[m][j] = sum_c A[m][c]*W[j][c] + bias[j]
// A row-major [M x 1024], W row-major [N x 1024]. Tile 128x128, BK=16.
// Double-buffered sync copies with register prefetch; direct LDS frag loads
// (pad-20 rows => conflict-free). 8 warps (2x4), 64x32 warp tiles.
// mode 0: scatter into per-head layout (z picks q/k/v)
// mode 1: A = g_x (resolved in DEVICE code), linear store to dlin.
// ---------------------------------------------------------------------------
#define BK    16
#define PADW  20
#define PLANE (128 * PADW)             // 2560 floats per plane
#define STAGE_FLOATS (4 * PLANE)       // Ah, Al, Bh, Bl
#define GEMM_SMEM_BYTES (2 * STAGE_FLOATS * 4)   // 81920 bytes

__device__ __forceinline__ void split_store(float* hi, float* lo, int off, float4 v) {
    float4 h = { tf32_rna(v.x), tf32_rna(v.y), tf32_rna(v.z), tf32_rna(v.w) };
    float4 l = { v.x - h.x, v.y - h.y, v.z - h.z, v.w - h.w };
    *(float4*)(hi + off) = h;
    *(float4*)(lo + off) = l;
}

__global__ void __launch_bounds__(256, 2) gemm_tc(
    const float* __restrict__ A0, const float* __restrict__ A1,
    const float* __restrict__ A2, const float* __restrict__ W,
    const float* __restrict__ bias, float* __restrict__ dlin, int mode)
{
    extern __shared__ float sg[];

    const int z = blockIdx.z;
    // Resolve A inside device code: mode 1 reads the __device__ scratch g_x.
    const float* Ain = (mode == 1) ? g_x
                     : (z == 0) ? A0 : (z == 1) ? A1 : A2;
    const float* Wp  = W + (size_t)z * C_DIM * C_DIM;
    const float* bp  = bias + z * C_DIM;

    const int m0 = blockIdx.y * 128;
    const int n0 = blockIdx.x * 128;
    const int tid  = threadIdx.x;
    const int wid  = tid >> 5;
    const int lane = tid & 31;
    const int warp_m = wid >> 2;    // 0..1 (64 rows each)
    const int warp_n = wid & 3;     // 0..3 (32 cols each)
    const int g   = lane >> 2;      // 0..7
    const int tig = lane & 3;       // 0..3

    // fill indices: thread covers rows fr0 and fr0+64, 4 floats at col fc0
    const int fr0 = tid >> 2;
    const int fc0 = (tid & 3) << 2;

    float acc[4][4][4];
#pragma unroll
    for (int i = 0; i < 4; i++)
#pragma unroll
        for (int j = 0; j < 4; j++)
#pragma unroll
            for (int c = 0; c < 4; c++) acc[i][j][c] = 0.f;

    float4 pa[2], pb[2];

#define LDG_TILE(kit) {                                                        \
        int _k0 = (kit) * BK;                                                  \
        pa[0] = *(const float4*)(Ain + (size_t)(m0 + fr0)      * C_DIM + _k0 + fc0); \
        pb[0] = *(const float4*)(Wp  + (size_t)(n0 + fr0)      * C_DIM + _k0 + fc0); \
        pa[1] = *(const float4*)(Ain + (size_t)(m0 + fr0 + 64) * C_DIM + _k0 + fc0); \
        pb[1] = *(const float4*)(Wp  + (size_t)(n0 + fr0 + 64) * C_DIM + _k0 + fc0); \
    }

#define STS_TILE(s) {                                                          \
        float* Ah = sg + (s) * STAGE_FLOATS;                                   \
        float* Al = Ah + PLANE;                                                \
        float* Bh = Ah + 2 * PLANE;                                            \
        float* Bl = Ah + 3 * PLANE;                                            \
        split_store(Ah, Al, fr0 * PADW + fc0,        pa[0]);                   \
        split_store(Ah, Al, (fr0 + 64) * PADW + fc0, pa[1]);                   \
        split_store(Bh, Bl, fr0 * PADW + fc0,        pb[0]);                   \
        split_store(Bh, Bl, (fr0 + 64) * PADW + fc0, pb[1]);                   \
    }

    const int NIT = C_DIM / BK;   // 64

    LDG_TILE(0);
    STS_TILE(0);
    __syncthreads();

    for (int it = 0; it < NIT; it++) {
        const int s = it & 1;
        const bool pf = (it + 1 < NIT);
        if (pf) LDG_TILE(it + 1);   // issue global loads early; overlap compute

        const float* Ah = sg + s * STAGE_FLOATS;
        const float* Al = Ah + PLANE;
        const float* Bh = Ah + 2 * PLANE;
        const float* Bl = Ah + 3 * PLANE;

#pragma unroll
        for (int k8 = 0; k8 < 2; k8++) {
            const int kc = k8 * 8 + tig;

            uint32_t bh[4][2], bl[4][2];
#pragma unroll
            for (int n8 = 0; n8 < 4; n8++) {
                int nb = (warp_n * 32 + n8 * 8 + g) * PADW;
                bh[n8][0] = __float_as_uint(Bh[nb + kc]);
                bh[n8][1] = __float_as_uint(Bh[nb + kc + 4]);
                bl[n8][0] = __float_as_uint(Bl[nb + kc]);
                bl[n8][1] = __float_as_uint(Bl[nb + kc + 4]);
            }
#pragma unroll
            for (int mt = 0; mt < 4; mt++) {
                int rb = (warp_m * 64 + mt * 16 + g) * PADW;
                uint32_t ah[4], al[4];
                ah[0] = __float_as_uint(Ah[rb + kc]);
                ah[1] = __float_as_uint(Ah[rb + 8 * PADW + kc]);
                ah[2] = __float_as_uint(Ah[rb + kc + 4]);
                ah[3] = __float_as_uint(Ah[rb + 8 * PADW + kc + 4]);
                al[0] = __float_as_uint(Al[rb + kc]);
                al[1] = __float_as_uint(Al[rb + 8 * PADW + kc]);
                al[2] = __float_as_uint(Al[rb + kc + 4]);
                al[3] = __float_as_uint(Al[rb + 8 * PADW + kc + 4]);
#pragma unroll
                for (int n8 = 0; n8 < 4; n8++) {
                    mma_tf32(acc[mt][n8], ah, bh[n8][0], bh[n8][1]);  // hi*hi
                    mma_tf32(acc[mt][n8], ah, bl[n8][0], bl[n8][1]);  // hi*lo
                    mma_tf32(acc[mt][n8], al, bh[n8][0], bh[n8][1]);  // lo*hi
                }
            }
        }
        __syncthreads();            // all reads of stage s done
        if (pf) STS_TILE((it + 1) & 1);
        __syncthreads();            // stage s^1 filled before next iter reads it
    }

    // Epilogue: mma D frag: c0,c1 = row lane/4, cols 2*(lane%4),+1; c2,c3 = row+8
    const int erow = lane >> 2;
    const int ecol = (lane & 3) * 2;
#pragma unroll
    for (int mt = 0; mt < 4; mt++) {
#pragma unroll
        for (int nt = 0; nt < 4; nt++) {
            int col = n0 + warp_n * 32 + nt * 8 + ecol;
            float bx = bp[col], by = bp[col + 1];
#pragma unroll
            for (int half = 0; half < 2; half++) {
                int m = m0 + warp_m * 64 + mt * 16 + erow + half * 8;
                float2 v = { acc[mt][nt][half * 2 + 0] + bx,
                             acc[mt][nt][half * 2 + 1] + by };
                if (mode == 0) {
                    int n = m >> 2, bb = m & 3;     // row m = n*B + b
                    int h = col >> 6, d = col & 63;
                    float* outp = ((z == 0) ? g_qs : (z == 1) ? g_ks : g_vs);
                    *(float2*)(outp + (((size_t)(bb * H_NUM + h) * N_SEQ) + n) * HD + d) = v;
                } else {
                    *(float2*)(dlin + (size_t)m * C_DIM + col) = v;
                }
            }
        }
    }
#undef LDG_TILE
#undef STS_TILE
}

// ---------------------------------------------------------------------------
// Kernel 2: L2-normalize each 64-vector of g_qs and g_ks.
// Fold exp(min(logit_scale, log100)) into q. One warp per row.
// ---------------------------------------------------------------------------
__global__ void __launch_bounds__(256) norm_kernel(const float* __restrict__ logit_scale)
{
    int wid = (blockIdx.x * blockDim.x + threadIdx.x) >> 5;
    int lane = threadIdx.x & 31;
    const int rows_per_tensor = BH * N_SEQ;  // 65536
    if (wid >= 2 * rows_per_tensor) return;
    int which = wid >= rows_per_tensor;
    int row = wid - which * rows_per_tensor;   // = bh*N + n
    float* ptr = (which ? g_ks : g_qs) + (size_t)row * HD;

    float x0 = ptr[lane];
    float x1 = ptr[lane + 32];
    float ss = x0 * x0 + x1 * x1;
#pragma unroll
    for (int o = 16; o > 0; o >>= 1) ss += __shfl_xor_sync(0xffffffffu, ss, o);
    float scale = 1.0f / fmaxf(sqrtf(ss), 1e-12f);
    if (!which) {
        int h = (row >> 10) & 15;   // bh = row>>10; h = bh % 16
        scale *= expf(fminf(logit_scale[h], LOGMAX));
    }
    ptr[lane]      = x0 * scale;
    ptr[lane + 32] = x1 * scale;
}

// ---------------------------------------------------------------------------
// Kernel 3: flash attention (fp32 SIMT). Block = 128 queries x one head.
// ---------------------------------------------------------------------------
#define QS(r, d) Qs[(r) * 65 + (d)]
#define KS(r, d) Ks[(r) * 65 + (d)]
#define VS(r, d) Vs[(r) * 65 + (d)]
#define PS(r, d) Ps[(r) * 65 + (d)]
#define ATTN_SMEM_BYTES (65 * (128 + 64 + 64 + 128) * 4)  // 99840 bytes

__global__ void __launch_bounds__(256, 2) attn_kernel()
{
    extern __shared__ float smf[];
    float* Qs = smf;                  // [128][65]
    float* Ks = Qs + 128 * 65;        // [64][65]
    float* Vs = Ks + 64 * 65;         // [64][65]
    float* Ps = Vs + 64 * 65;         // [128][65]

    const int bh = blockIdx.y;
    const int n0 = blockIdx.x * 128;
    const int tid = threadIdx.x;
    const int ty4 = (tid >> 4) * 4;
    const int tx4 = (tid & 15) * 4;

    const float* qbase = g_qs + ((size_t)bh * N_SEQ + n0) * HD;
    const float* kbase = g_ks + (size_t)bh * N_SEQ * HD;
    const float* vbase = g_vs + (size_t)bh * N_SEQ * HD;

    int rows[8];
#pragma unroll
    for (int i = 0; i < 4; i++) { rows[i] = ty4 + i; rows[i + 4] = 64 + ty4 + i; }

#pragma unroll
    for (int u = 0; u < 8; u++) {
        int f = tid + 256 * u;
        int r = f >> 4;
        int d0 = (f & 15) << 2;
        float4 v = *(const float4*)(qbase + r * HD + d0);
        QS(r, d0 + 0) = v.x; QS(r, d0 + 1) = v.y;
        QS(r, d0 + 2) = v.z; QS(r, d0 + 3) = v.w;
    }

    float m_[8], l_[8], o_[8][4];
#pragma unroll
    for (int i = 0; i < 8; i++) {
        m_[i] = -3.0e38f; l_[i] = 0.f;
#pragma unroll
        for (int j = 0; j < 4; j++) o_[i][j] = 0.f;
    }

    for (int kt = 0; kt < N_SEQ / 64; kt++) {
        __syncthreads();
        const float* kb = kbase + kt * 64 * HD;
        const float* vb = vbase + kt * 64 * HD;
#pragma unroll
        for (int u = 0; u < 4; u++) {
            int f = tid + 256 * u;
            int r = f >> 4;
            int d0 = (f & 15) << 2;
            float4 vk = *(const float4*)(kb + r * HD + d0);
            KS(r, d0 + 0) = vk.x; KS(r, d0 + 1) = vk.y;
            KS(r, d0 + 2) = vk.z; KS(r, d0 + 3) = vk.w;
            float4 vv = *(const float4*)(vb + r * HD + d0);
            VS(r, d0 + 0) = vv.x; VS(r, d0 + 1) = vv.y;
            VS(r, d0 + 2) = vv.z; VS(r, d0 + 3) = vv.w;
        }
        __syncthreads();

        float s[8][4];
#pragma unroll
        for (int i = 0; i < 8; i++)
#pragma unroll
            for (int j = 0; j < 4; j++) s[i][j] = 0.f;
#pragma unroll 8
        for (int d = 0; d < HD; d++) {
            float a[8], b[4];
#pragma unroll
            for (int i = 0; i < 8; i++) a[i] = QS(rows[i], d);
#pragma unroll
            for (int j = 0; j < 4; j++) b[j] = KS(tx4 + j, d);
#pragma unroll
            for (int i = 0; i < 8; i++)
#pragma unroll
                for (int j = 0; j < 4; j++) s[i][j] = fmaf(a[i], b[j], s[i][j]);
        }

#pragma unroll
        for (int i = 0; i < 8; i++) {
            float tmax = fmaxf(fmaxf(s[i][0], s[i][1]), fmaxf(s[i][2], s[i][3]));
#pragma unroll
            for (int o = 8; o > 0; o >>= 1)
                tmax = fmaxf(tmax, __shfl_xor_sync(0xffffffffu, tmax, o));
            float mn = fmaxf(m_[i], tmax);
            float corr = __expf(m_[i] - mn);
            float rs = 0.f;
#pragma unroll
            for (int j = 0; j < 4; j++) { s[i][j] = __expf(s[i][j] - mn); rs += s[i][j]; }
#pragma unroll
            for (int o = 8; o > 0; o >>= 1)
                rs += __shfl_xor_sync(0xffffffffu, rs, o);
            l_[i] = l_[i] * corr + rs;
            m_[i] = mn;
#pragma unroll
            for (int j = 0; j < 4; j++) o_[i][j] *= corr;
        }

#pragma unroll
        for (int i = 0; i < 8; i++)
#pragma unroll
            for (int j = 0; j < 4; j++) PS(rows[i], tx4 + j) = s[i][j];
        __syncthreads();

#pragma unroll 8
        for (int k = 0; k < 64; k++) {
            float a[8], b[4];
#pragma unroll
            for (int i = 0; i < 8; i++) a[i] = PS(rows[i], k);
#pragma unroll
            for (int j = 0; j < 4; j++) b[j] = VS(k, tx4 + j);
#pragma unroll
            for (int i = 0; i < 8; i++)
#pragma unroll
                for (int j = 0; j < 4; j++) o_[i][j] = fmaf(a[i], b[j], o_[i][j]);
        }
    }

    const int bb = bh >> 4;
    const int h  = bh & 15;
#pragma unroll
    for (int i = 0; i < 8; i++) {
        float inv = 1.0f / l_[i];
        int n = n0 + rows[i];
#pragma unroll
        for (int j = 0; j < 4; j++) {
            g_x[((size_t)n * B_SZ + bb) * C_DIM + h * HD + tx4 + j] = o_[i][j] * inv;
        }
    }
}

// ---------------------------------------------------------------------------
extern "C" void kernel_launch(void* const* d_in, const int* in_sizes, int n_in,
                              void* d_out, int out_size)
{
    const float* q     = (const float*)d_in[0];
    const float* k     = (const float*)d_in[1];
    const float* v     = (const float*)d_in[2];
    const float* w_in  = (const float*)d_in[3];
    const float* b_in  = (const float*)d_in[4];
    const float* ls    = (const float*)d_in[5];
    const float* w_out = (const float*)d_in[6];
    const float* b_out = (const float*)d_in[7];
    float* out = (float*)d_out;

    cudaFuncSetAttribute(gemm_tc,
                         cudaFuncAttributeMaxDynamicSharedMemorySize,
                         GEMM_SMEM_BYTES);
    cudaFuncSetAttribute(attn_kernel,
                         cudaFuncAttributeMaxDynamicSharedMemorySize,
                         ATTN_SMEM_BYTES);

    // QKV projection (z = 0/1/2 -> q/k/v), scatter into head layout
    gemm_tc<<<dim3(C_DIM / 128, M_ROWS / 128, 3), 256, GEMM_SMEM_BYTES>>>(
        q, k, v, w_in, b_in, nullptr, 0);
    norm_kernel<<<(2 * BH * N_SEQ) / 8, 256>>>(ls);
    attn_kernel<<<dim3(N_SEQ / 128, BH), 256, ATTN_SMEM_BYTES>>>();
    // Output projection: A resolved to g_x inside device code (mode 1)
    gemm_tc<<<dim3(C_DIM / 128, M_ROWS / 128, 1), 256, GEMM_SMEM_BYTES>>>(
        nullptr, nullptr, nullptr, w_out, b_out, out, 1);
}

// round 6
// speedup vs baseline: 2.3798x; 1.7110x over previous
#include <cuda_runtime.h>
#include <cuda_bf16.h>
#include <math.h>
#include <stdint.h>

// Problem constants
#define N_SEQ  1024
#define B_SZ   4
#define C_DIM  1024
#define H_NUM  16
#define HD     64
#define BH     64          // B*H
#define M_ROWS 4096        // N*B
#define LOGMAX 4.6051701859880913680f  // log(100)
#define LOG2E  1.4426950408889634f

// Scratch (static device arrays -- no allocations allowed)
__device__ float g_qs[BH * N_SEQ * HD];  // fp32 [bh][n][d] (pre-norm q)
__device__ float g_ks[BH * N_SEQ * HD];
__device__ float g_x [M_ROWS * C_DIM];   // attention output, (N,B,C)

// Packed bf16 hi/lo words (2 bf16 per uint32, even/odd d or n pairs)
__device__ uint32_t g_qh[BH * N_SEQ * 32];   // [bh][n][dword]
__device__ uint32_t g_ql[BH * N_SEQ * 32];
__device__ uint32_t g_kh[BH * N_SEQ * 32];
__device__ uint32_t g_kl[BH * N_SEQ * 32];
__device__ __align__(16) __nv_bfloat16 g_vh16[BH * HD * N_SEQ];  // [bh][d][n] transposed V hi
__device__ __align__(16) __nv_bfloat16 g_vl16[BH * HD * N_SEQ];  // lo

// ---------------------------------------------------------------------------
// Helpers (plain-target PTX only)
// ---------------------------------------------------------------------------
__device__ __forceinline__ void mma_bf16(float* d, const uint32_t* a,
                                         uint32_t b0, uint32_t b1) {
    asm volatile(
        "mma.sync.aligned.m16n8k16.row.col.f32.bf16.bf16.f32 "
        "{%0,%1,%2,%3}, {%4,%5,%6,%7}, {%8,%9}, {%0,%1,%2,%3};"
        : "+f"(d[0]), "+f"(d[1]), "+f"(d[2]), "+f"(d[3])
        : "r"(a[0]), "r"(a[1]), "r"(a[2]), "r"(a[3]), "r"(b0), "r"(b1));
}

__device__ __forceinline__ uint32_t pack_bf2(float x, float y) {
    uint16_t lx = __bfloat16_as_ushort(__float2bfloat16_rn(x));
    uint16_t ly = __bfloat16_as_ushort(__float2bfloat16_rn(y));
    return (uint32_t)lx | ((uint32_t)ly << 16);
}

// split pair (x,y) -> hi word + lo word
__device__ __forceinline__ void split2(float x, float y, uint32_t& hw, uint32_t& lw) {
    float hx = __bfloat162float(__float2bfloat16_rn(x));
    float hy = __bfloat162float(__float2bfloat16_rn(y));
    hw = pack_bf2(hx, hy);
    lw = pack_bf2(x - hx, y - hy);
}

__device__ __forceinline__ float fast_exp2(float x) {
    float y;
    asm("ex2.approx.f32 %0, %1;" : "=f"(y) : "f"(x));
    return y;
}

// ---------------------------------------------------------------------------
// Tensor-core GEMM with 3xBF16 (hi*hi + hi*lo + lo*hi):
//   C[m][j] = sum_c A[m][c]*W[j][c] + bias[j]
// Tile 128x128, BK=32, single-sync double buffer, 8 warps (2x4), 64x32 warp
// tiles, mma m16n8k16.bf16. Smem 32-bit stride 20 (proven conflict-free).
// mode 0: scatter q/k to fp32 head layout; z==2 (v): transposed bf16 hi/lo.
// mode 1: A = g_x (device-resolved), linear fp32 store to dlin.
// ---------------------------------------------------------------------------
#define SW      20                       // 32-bit words per row (16 data + 4 pad)
#define PLANE_W (128 * SW)               // 2560 words per plane
#define STAGE_W (4 * PLANE_W)            // Ah, Al, Bh, Bl
#define GEMM_SMEM_BYTES (2 * STAGE_W * 4)   // 81920 bytes

__global__ void __launch_bounds__(256, 2) gemm_tc(
    const float* __restrict__ A0, const float* __restrict__ A1,
    const float* __restrict__ A2, const float* __restrict__ W,
    const float* __restrict__ bias, float* __restrict__ dlin, int mode)
{
    extern __shared__ uint32_t sg[];

    const int z = blockIdx.z;
    const float* Ain = (mode == 1) ? g_x
                     : (z == 0) ? A0 : (z == 1) ? A1 : A2;
    const float* Wp  = W + (size_t)z * C_DIM * C_DIM;
    const float* bp  = bias + z * C_DIM;

    const int m0 = blockIdx.y * 128;
    const int n0 = blockIdx.x * 128;
    const int tid  = threadIdx.x;
    const int wid  = tid >> 5;
    const int lane = tid & 31;
    const int warp_m = wid >> 2;    // 0..1 (64 rows)
    const int warp_n = wid & 3;     // 0..3 (32 cols)
    const int g   = lane >> 2;      // 0..7
    const int tig = lane & 3;       // 0..3

    float acc[4][4][4];
#pragma unroll
    for (int i = 0; i < 4; i++)
#pragma unroll
        for (int j = 0; j < 4; j++)
#pragma unroll
            for (int c = 0; c < 4; c++) acc[i][j][c] = 0.f;

    float4 pa[4], pb[4];

#define LDG_TILE(kit) {                                                         \
        int _k0 = (kit) * 32;                                                   \
        _Pragma("unroll")                                                       \
        for (int u = 0; u < 4; u++) {                                           \
            int f = tid + 256 * u;                                              \
            int r = f >> 3, c4 = (f & 7) << 2;                                  \
            pa[u] = *(const float4*)(Ain + (size_t)(m0 + r) * C_DIM + _k0 + c4);\
            pb[u] = *(const float4*)(Wp  + (size_t)(n0 + r) * C_DIM + _k0 + c4);\
        }                                                                       \
    }

#define STS_TILE(s) {                                                           \
        uint32_t* Ah = sg + (s) * STAGE_W;                                      \
        uint32_t* Al = Ah + PLANE_W;                                            \
        uint32_t* Bh = Ah + 2 * PLANE_W;                                        \
        uint32_t* Bl = Ah + 3 * PLANE_W;                                        \
        _Pragma("unroll")                                                       \
        for (int u = 0; u < 4; u++) {                                           \
            int f = tid + 256 * u;                                              \
            int r = f >> 3;                                                     \
            int w = r * SW + ((f & 7) << 1);                                    \
            uint32_t h0, l0, h1, l1;                                            \
            split2(pa[u].x, pa[u].y, h0, l0);                                   \
            split2(pa[u].z, pa[u].w, h1, l1);                                   \
            Ah[w] = h0; Ah[w + 1] = h1; Al[w] = l0; Al[w + 1] = l1;             \
            split2(pb[u].x, pb[u].y, h0, l0);                                   \
            split2(pb[u].z, pb[u].w, h1, l1);                                   \
            Bh[w] = h0; Bh[w + 1] = h1; Bl[w] = l0; Bl[w + 1] = l1;             \
        }                                                                       \
    }

    const int NIT = C_DIM / 32;   // 32

    LDG_TILE(0);
    STS_TILE(0);
    __syncthreads();

    for (int it = 0; it < NIT; it++) {
        const int s = it & 1;
        const bool pf = (it + 1 < NIT);
        if (pf) LDG_TILE(it + 1);

        const uint32_t* Ah = sg + s * STAGE_W;
        const uint32_t* Al = Ah + PLANE_W;
        const uint32_t* Bh = Ah + 2 * PLANE_W;
        const uint32_t* Bl = Ah + 3 * PLANE_W;

#pragma unroll
        for (int ks = 0; ks < 2; ks++) {
            const int kw = ks * 8 + tig;

            uint32_t bh[4][2], bl[4][2];
#pragma unroll
            for (int n8 = 0; n8 < 4; n8++) {
                int nb = (warp_n * 32 + n8 * 8 + g) * SW;
                bh[n8][0] = Bh[nb + kw];  bh[n8][1] = Bh[nb + kw + 4];
                bl[n8][0] = Bl[nb + kw];  bl[n8][1] = Bl[nb + kw + 4];
            }
#pragma unroll
            for (int mt = 0; mt < 4; mt++) {
                int rb = (warp_m * 64 + mt * 16 + g) * SW;
                uint32_t ah[4], al[4];
                ah[0] = Ah[rb + kw];            ah[1] = Ah[rb + 8 * SW + kw];
                ah[2] = Ah[rb + kw + 4];        ah[3] = Ah[rb + 8 * SW + kw + 4];
                al[0] = Al[rb + kw];            al[1] = Al[rb + 8 * SW + kw];
                al[2] = Al[rb + kw + 4];        al[3] = Al[rb + 8 * SW + kw + 4];
#pragma unroll
                for (int n8 = 0; n8 < 4; n8++) {
                    mma_bf16(acc[mt][n8], ah, bh[n8][0], bh[n8][1]);  // hi*hi
                    mma_bf16(acc[mt][n8], ah, bl[n8][0], bl[n8][1]);  // hi*lo
                    mma_bf16(acc[mt][n8], al, bh[n8][0], bh[n8][1]);  // lo*hi
                }
            }
        }
        if (pf) STS_TILE(s ^ 1);
        __syncthreads();
    }

    // Epilogue. D frag: c0,c1 = (row g, cols 2tig,2tig+1); c2,c3 = row+8.
    const int erow = lane >> 2;
    const int ecol = (lane & 3) * 2;
#pragma unroll
    for (int mt = 0; mt < 4; mt++) {
#pragma unroll
        for (int nt = 0; nt < 4; nt++) {
            int col = n0 + warp_n * 32 + nt * 8 + ecol;
            float bx = bp[col], by = bp[col + 1];
#pragma unroll
            for (int half = 0; half < 2; half++) {
                int m = m0 + warp_m * 64 + mt * 16 + erow + half * 8;
                float v0 = acc[mt][nt][half * 2 + 0] + bx;
                float v1 = acc[mt][nt][half * 2 + 1] + by;
                if (mode == 0) {
                    int n = m >> 2, bb = m & 3;     // row m = n*B + b
                    int h = col >> 6, d = col & 63;
                    if (z == 2) {
                        // V: transposed bf16 hi/lo  [bh][d][n]
                        size_t base = ((size_t)(bb * H_NUM + h) * HD + d) * N_SEQ + n;
                        float h0 = __bfloat162float(__float2bfloat16_rn(v0));
                        float h1 = __bfloat162float(__float2bfloat16_rn(v1));
                        g_vh16[base]         = __float2bfloat16_rn(v0);
                        g_vl16[base]         = __float2bfloat16_rn(v0 - h0);
                        g_vh16[base + N_SEQ] = __float2bfloat16_rn(v1);
                        g_vl16[base + N_SEQ] = __float2bfloat16_rn(v1 - h1);
                    } else {
                        float* outp = (z == 0) ? g_qs : g_ks;
                        float2 v = { v0, v1 };
                        *(float2*)(outp + (((size_t)(bb * H_NUM + h) * N_SEQ) + n) * HD + d) = v;
                    }
                } else {
                    float2 v = { v0, v1 };
                    *(float2*)(dlin + (size_t)m * C_DIM + col) = v;
                }
            }
        }
    }
#undef LDG_TILE
#undef STS_TILE
}

// ---------------------------------------------------------------------------
// Kernel 2: L2-normalize q/k rows, fold exp(min(ls,log100))*log2e into q,
// emit packed bf16 hi/lo words. One warp per row; lane owns d=2*lane,2*lane+1.
// ---------------------------------------------------------------------------
__global__ void __launch_bounds__(256) norm_kernel(const float* __restrict__ logit_scale)
{
    int wrow = (blockIdx.x * blockDim.x + threadIdx.x) >> 5;
    int lane = threadIdx.x & 31;
    const int rows_per_tensor = BH * N_SEQ;  // 65536
    if (wrow >= 2 * rows_per_tensor) return;
    int which = wrow >= rows_per_tensor;
    int row = wrow - which * rows_per_tensor;   // = bh*N + n
    const float* ptr = (which ? g_ks : g_qs) + (size_t)row * HD;

    float x0 = ptr[2 * lane];
    float x1 = ptr[2 * lane + 1];
    float ss = x0 * x0 + x1 * x1;
#pragma unroll
    for (int o = 16; o > 0; o >>= 1) ss += __shfl_xor_sync(0xffffffffu, ss, o);
    float scale = 1.0f / fmaxf(sqrtf(ss), 1e-12f);
    if (!which) {
        int h = (row >> 10) & 15;
        scale *= expf(fminf(logit_scale[h], LOGMAX)) * LOG2E;  // softmax in base-2
    }
    uint32_t hw, lw;
    split2(x0 * scale, x1 * scale, hw, lw);
    uint32_t* dh = which ? g_kh : g_qh;
    uint32_t* dl = which ? g_kl : g_ql;
    dh[(size_t)row * 32 + lane] = hw;
    dl[(size_t)row * 32 + lane] = lw;
}

// ---------------------------------------------------------------------------
// Kernel 3: tensor-core flash attention. Block = 128 q x one head; 8 warps,
// each owns 16 complete query rows (softmax fully warp-local).
// QK: 3xbf16 (q hi/lo x k hi/lo). PV: P split in registers (S-frag cols map
// directly onto A-frag k), V pre-transposed bf16 hi/lo.
// ---------------------------------------------------------------------------
#define AW    36                         // 32-bit words per smem row (32 + 4 pad)
#define Q_H   0
#define Q_L   (128 * AW)
#define K_H   (2 * 128 * AW)
#define K_L   (K_H + 64 * AW)
#define V_H   (K_L + 64 * AW)
#define V_L   (V_H + 64 * AW)
#define ATTN_SMEM_WORDS (V_L + 64 * AW)              // 18432 words
#define ATTN_SMEM_BYTES (ATTN_SMEM_WORDS * 4)        // 73728 bytes

__global__ void __launch_bounds__(256, 2) attn_kernel()
{
    extern __shared__ uint32_t sa[];

    const int bh = blockIdx.y;
    const int n0 = blockIdx.x * 128;
    const int tid  = threadIdx.x;
    const int warp = tid >> 5;
    const int lane = tid & 31;
    const int g    = lane >> 2;
    const int tig  = lane & 3;
    const int qr   = warp * 16;          // warp's query-row base within tile

    const size_t qrow0 = (size_t)bh * N_SEQ + n0;
    const size_t krow0 = (size_t)bh * N_SEQ;
    const size_t vrow0 = (size_t)bh * HD;          // rows are d
    const uint32_t* vwh = (const uint32_t*)g_vh16;
    const uint32_t* vwl = (const uint32_t*)g_vl16;

    // Stage Q tile (128 rows x 32 words, hi+lo)
#pragma unroll
    for (int u = 0; u < 4; u++) {
        int f = tid + 256 * u;
        int r = f >> 3, w4 = (f & 7) << 2;
        *(uint4*)&sa[Q_H + r * AW + w4] = *(const uint4*)&g_qh[(qrow0 + r) * 32 + w4];
        *(uint4*)&sa[Q_L + r * AW + w4] = *(const uint4*)&g_ql[(qrow0 + r) * 32 + w4];
    }

    float m0 = -1e30f, m1 = -1e30f, l0 = 0.f, l1 = 0.f;
    float o_acc[8][4];
#pragma unroll
    for (int i = 0; i < 8; i++)
#pragma unroll
        for (int c = 0; c < 4; c++) o_acc[i][c] = 0.f;

    for (int kt = 0; kt < N_SEQ / 64; kt++) {
        __syncthreads();   // K/V buffer reuse guard (also orders Q staging on kt==0)
#pragma unroll
        for (int u = 0; u < 2; u++) {
            int f = tid + 256 * u;
            int r = f >> 3, w4 = (f & 7) << 2;
            *(uint4*)&sa[K_H + r * AW + w4] = *(const uint4*)&g_kh[(krow0 + kt * 64 + r) * 32 + w4];
            *(uint4*)&sa[K_L + r * AW + w4] = *(const uint4*)&g_kl[(krow0 + kt * 64 + r) * 32 + w4];
            *(uint4*)&sa[V_H + r * AW + w4] = *(const uint4*)&vwh[(vrow0 + r) * 512 + kt * 32 + w4];
            *(uint4*)&sa[V_L + r * AW + w4] = *(const uint4*)&vwl[(vrow0 + r) * 512 + kt * 32 + w4];
        }
        __syncthreads();

        // ---- S = Q K^T (rows qr..qr+15, keys 0..63 of tile), 3xbf16 ----
        float s_acc[8][4];
#pragma unroll
        for (int i = 0; i < 8; i++)
#pragma unroll
            for (int c = 0; c < 4; c++) s_acc[i][c] = 0.f;

#pragma unroll
        for (int s = 0; s < 4; s++) {          // k16 over d
            const int kw = s * 8 + tig;
            const int rb = (qr + g) * AW;
            uint32_t qh[4], ql[4];
            qh[0] = sa[Q_H + rb + kw];          qh[1] = sa[Q_H + rb + 8 * AW + kw];
            qh[2] = sa[Q_H + rb + kw + 4];      qh[3] = sa[Q_H + rb + 8 * AW + kw + 4];
            ql[0] = sa[Q_L + rb + kw];          ql[1] = sa[Q_L + rb + 8 * AW + kw];
            ql[2] = sa[Q_L + rb + kw + 4];      ql[3] = sa[Q_L + rb + 8 * AW + kw + 4];
#pragma unroll
            for (int nt = 0; nt < 8; nt++) {   // 8-key groups
                int kb = (nt * 8 + g) * AW;
                uint32_t kh0 = sa[K_H + kb + kw], kh1 = sa[K_H + kb + kw + 4];
                uint32_t kl0 = sa[K_L + kb + kw], kl1 = sa[K_L + kb + kw + 4];
                mma_bf16(s_acc[nt], qh, kh0, kh1);
                mma_bf16(s_acc[nt], qh, kl0, kl1);
                mma_bf16(s_acc[nt], ql, kh0, kh1);
            }
        }

        // ---- online softmax (base-2; scale folded into q) ----
        float rmax0 = -1e30f, rmax1 = -1e30f;
#pragma unroll
        for (int nt = 0; nt < 8; nt++) {
            rmax0 = fmaxf(rmax0, fmaxf(s_acc[nt][0], s_acc[nt][1]));
            rmax1 = fmaxf(rmax1, fmaxf(s_acc[nt][2], s_acc[nt][3]));
        }
        rmax0 = fmaxf(rmax0, __shfl_xor_sync(0xffffffffu, rmax0, 1));
        rmax0 = fmaxf(rmax0, __shfl_xor_sync(0xffffffffu, rmax0, 2));
        rmax1 = fmaxf(rmax1, __shfl_xor_sync(0xffffffffu, rmax1, 1));
        rmax1 = fmaxf(rmax1, __shfl_xor_sync(0xffffffffu, rmax1, 2));
        float mn0 = fmaxf(m0, rmax0), mn1 = fmaxf(m1, rmax1);
        float corr0 = fast_exp2(m0 - mn0), corr1 = fast_exp2(m1 - mn1);
        float rs0 = 0.f, rs1 = 0.f;
#pragma unroll
        for (int nt = 0; nt < 8; nt++) {
            s_acc[nt][0] = fast_exp2(s_acc[nt][0] - mn0);
            s_acc[nt][1] = fast_exp2(s_acc[nt][1] - mn0);
            s_acc[nt][2] = fast_exp2(s_acc[nt][2] - mn1);
            s_acc[nt][3] = fast_exp2(s_acc[nt][3] - mn1);
            rs0 += s_acc[nt][0] + s_acc[nt][1];
            rs1 += s_acc[nt][2] + s_acc[nt][3];
        }
        rs0 += __shfl_xor_sync(0xffffffffu, rs0, 1);
        rs0 += __shfl_xor_sync(0xffffffffu, rs0, 2);
        rs1 += __shfl_xor_sync(0xffffffffu, rs1, 1);
        rs1 += __shfl_xor_sync(0xffffffffu, rs1, 2);
        l0 = l0 * corr0 + rs0;  m0 = mn0;
        l1 = l1 * corr1 + rs1;  m1 = mn1;
#pragma unroll
        for (int nt = 0; nt < 8; nt++) {
            o_acc[nt][0] *= corr0;  o_acc[nt][1] *= corr0;
            o_acc[nt][2] *= corr1;  o_acc[nt][3] *= corr1;
        }

        // ---- O += P V : P A-frags straight from S accumulators ----
#pragma unroll
        for (int s = 0; s < 4; s++) {          // k16 over keys
            uint32_t pah[4], pal[4];
            split2(s_acc[2 * s][0],     s_acc[2 * s][1],     pah[0], pal[0]);
            split2(s_acc[2 * s][2],     s_acc[2 * s][3],     pah[1], pal[1]);
            split2(s_acc[2 * s + 1][0], s_acc[2 * s + 1][1], pah[2], pal[2]);
            split2(s_acc[2 * s + 1][2], s_acc[2 * s + 1][3], pah[3], pal[3]);
            const int kw = s * 8 + tig;
#pragma unroll
            for (int nt = 0; nt < 8; nt++) {   // 8-d groups
                int vb = (nt * 8 + g) * AW;
                uint32_t vh0 = sa[V_H + vb + kw], vh1 = sa[V_H + vb + kw + 4];
                uint32_t vl0 = sa[V_L + vb + kw], vl1 = sa[V_L + vb + kw + 4];
                mma_bf16(o_acc[nt], pah, vh0, vh1);
                mma_bf16(o_acc[nt], pah, vl0, vl1);
                mma_bf16(o_acc[nt], pal, vh0, vh1);
            }
        }
    }

    // Epilogue: out[q][d] = o/l into (N,B,C) layout
    const int bb = bh >> 4;
    const int h  = bh & 15;
    float inv0 = 1.0f / l0, inv1 = 1.0f / l1;
    int nq0 = n0 + qr + g;
#pragma unroll
    for (int nt = 0; nt < 8; nt++) {
        int d = nt * 8 + 2 * tig;
        float2 v0 = { o_acc[nt][0] * inv0, o_acc[nt][1] * inv0 };
        float2 v1 = { o_acc[nt][2] * inv1, o_acc[nt][3] * inv1 };
        *(float2*)(g_x + ((size_t)nq0 * B_SZ + bb) * C_DIM + h * HD + d) = v0;
        *(float2*)(g_x + ((size_t)(nq0 + 8) * B_SZ + bb) * C_DIM + h * HD + d) = v1;
    }
}

// ---------------------------------------------------------------------------
extern "C" void kernel_launch(void* const* d_in, const int* in_sizes, int n_in,
                              void* d_out, int out_size)
{
    const float* q     = (const float*)d_in[0];
    const float* k     = (const float*)d_in[1];
    const float* v     = (const float*)d_in[2];
    const float* w_in  = (const float*)d_in[3];
    const float* b_in  = (const float*)d_in[4];
    const float* ls    = (const float*)d_in[5];
    const float* w_out = (const float*)d_in[6];
    const float* b_out = (const float*)d_in[7];
    float* out = (float*)d_out;

    cudaFuncSetAttribute(gemm_tc,
                         cudaFuncAttributeMaxDynamicSharedMemorySize,
                         GEMM_SMEM_BYTES);
    cudaFuncSetAttribute(attn_kernel,
                         cudaFuncAttributeMaxDynamicSharedMemorySize,
                         ATTN_SMEM_BYTES);

    gemm_tc<<<dim3(C_DIM / 128, M_ROWS / 128, 3), 256, GEMM_SMEM_BYTES>>>(
        q, k, v, w_in, b_in, nullptr, 0);
    norm_kernel<<<(2 * BH * N_SEQ) / 8, 256>>>(ls);
    attn_kernel<<<dim3(N_SEQ / 128, BH), 256, ATTN_SMEM_BYTES>>>();
    gemm_tc<<<dim3(C_DIM / 128, M_ROWS / 128, 1), 256, GEMM_SMEM_BYTES>>>(
        nullptr, nullptr, nullptr, w_out, b_out, out, 1);
}